// round 1
// baseline (speedup 1.0000x reference)
#include <cuda_runtime.h>
#include <math.h>

#define MDIM 512
#define LDIM 31
#define CTOT 542                 // MDIM + LDIM - 1
#define NX   1024
#define ROWE (NX * LDIM)         // 31744 floats per input row strip
#define XCE  (MDIM * LDIM)       // 15872 floats per output row strip
#define SMEM_FWD ((ROWE + XCE + 32) * sizeof(float))

// Scratch (statically allocated: no runtime allocation allowed)
__device__ float    g_yn[MDIM * CTOT];
__device__ unsigned g_key[2];    // [0]: max(yn), [1]: max(X2)  (order-preserving uint keys)

__device__ __forceinline__ unsigned fkey(float x) {
    unsigned u = __float_as_uint(x);
    return (u & 0x80000000u) ? ~u : (u | 0x80000000u);
}
__device__ __forceinline__ float fkey_inv(unsigned k) {
    unsigned u = (k & 0x80000000u) ? (k & 0x7FFFFFFFu) : ~k;
    return __uint_as_float(u);
}

__global__ void k_init() { g_key[0] = 0u; g_key[1] = 0u; }

// One block per output row r. Fuses: row-resize, col-resize, lambda-conv,
// H multiply, yn skew-sum, row max.
__global__ void __launch_bounds__(1024) k_forward(const float* __restrict__ X,
                                                  const float* __restrict__ H) {
    extern __shared__ float sm[];
    float* sT   = sm;               // ROWE floats: row-resized strip; later reused as sP
    float* sXR  = sm + ROWE;        // XCE floats: col-resized (Xr row)
    float* sRed = sXR + XCE;        // 32 floats: reduction scratch

    const int r   = blockIdx.x;
    const int tid = threadIdx.x;
    const int nt  = blockDim.x;

    // ---- Phase 0: antialiased bilinear row resize (axis 1), 4 taps ----
    float w0, w1, w2, w3;
    int i0, i1, i2, i3;
    if (r == 0) {
        w0 = 0.f;      w1 = 3.f/7.f; w2 = 3.f/7.f; w3 = 1.f/7.f;
        i0 = 0; i1 = 0; i2 = 1; i3 = 2;
    } else if (r == MDIM - 1) {
        w0 = 1.f/7.f;  w1 = 3.f/7.f; w2 = 3.f/7.f; w3 = 0.f;
        i0 = 2*r - 1; i1 = 2*r; i2 = 2*r + 1; i3 = 2*r + 1;   // dummy row, weight 0
    } else {
        w0 = 0.125f;   w1 = 0.375f;  w2 = 0.375f;  w3 = 0.125f;
        i0 = 2*r - 1; i1 = 2*r; i2 = 2*r + 1; i3 = 2*r + 2;
    }
    const float4* X0 = (const float4*)(X + (size_t)i0 * ROWE);
    const float4* X1 = (const float4*)(X + (size_t)i1 * ROWE);
    const float4* X2 = (const float4*)(X + (size_t)i2 * ROWE);
    const float4* X3 = (const float4*)(X + (size_t)i3 * ROWE);
    float4* sT4 = (float4*)sT;
    for (int j = tid; j < ROWE / 4; j += nt) {
        float4 a = X0[j], b = X1[j], c = X2[j], d = X3[j];
        float4 o;
        o.x = w0*a.x + w1*b.x + w2*c.x + w3*d.x;
        o.y = w0*a.y + w1*b.y + w2*c.y + w3*d.y;
        o.z = w0*a.z + w1*b.z + w2*c.z + w3*d.z;
        o.w = w0*a.w + w1*b.w + w2*c.w + w3*d.w;
        sT4[j] = o;
    }
    __syncthreads();

    // ---- Phase 1: antialiased bilinear column resize (axis 2) ----
    for (int e = tid; e < XCE; e += nt) {
        int c = e / LDIM;
        int l = e - c * LDIM;
        float v;
        if (c == 0) {
            v = (3.f/7.f)*sT[l] + (3.f/7.f)*sT[LDIM + l] + (1.f/7.f)*sT[2*LDIM + l];
        } else if (c == MDIM - 1) {
            v = (1.f/7.f)*sT[(NX-3)*LDIM + l] + (3.f/7.f)*sT[(NX-2)*LDIM + l]
              + (3.f/7.f)*sT[(NX-1)*LDIM + l];
        } else {
            int b = (2*c - 1) * LDIM + l;
            v = 0.125f*sT[b] + 0.375f*sT[b + LDIM] + 0.375f*sT[b + 2*LDIM] + 0.125f*sT[b + 3*LDIM];
        }
        sXR[e] = v;
    }
    __syncthreads();

    // ---- Phase 2: lambda conv [1/4,1/2,1/4] along L (zero pad) * H -> sP (reuses sT) ----
    const float* Hr = H + (size_t)r * XCE;
    float* sP = sT;
    for (int e = tid; e < XCE; e += nt) {
        int c = e / LDIM;
        int l = e - c * LDIM;
        float v = 0.5f * sXR[e];
        if (l > 0)        v += 0.25f * sXR[e - 1];
        if (l < LDIM - 1) v += 0.25f * sXR[e + 1];
        sP[e] = Hr[e] * v;
    }
    __syncthreads();

    // ---- Phase 3: yn[c'] = sum_i P[c'-i, i]  (skewed sum; mod-wrap hits pad zeros) ----
    float lmax = -INFINITY;
    float* ynr = g_yn + r * CTOT;
    for (int cc = tid; cc < CTOT; cc += nt) {
        int ilo = cc - (MDIM - 1); if (ilo < 0) ilo = 0;
        int ihi = (cc < LDIM - 1) ? cc : (LDIM - 1);
        float acc = 0.f;
        for (int i = ilo; i <= ihi; ++i)
            acc += sP[(cc - i) * LDIM + i];
        ynr[cc] = acc;
        lmax = fmaxf(lmax, acc);
    }

    // ---- block max reduce -> atomicMax on ordered key ----
    int lane = tid & 31, wid = tid >> 5;
    #pragma unroll
    for (int off = 16; off; off >>= 1)
        lmax = fmaxf(lmax, __shfl_xor_sync(0xffffffffu, lmax, off));
    if (lane == 0) sRed[wid] = lmax;
    __syncthreads();
    if (wid == 0) {
        float v = (lane < (nt >> 5)) ? sRed[lane] : -INFINITY;
        #pragma unroll
        for (int off = 16; off; off >>= 1)
            v = fmaxf(v, __shfl_xor_sync(0xffffffffu, v, off));
        if (lane == 0) atomicMax(&g_key[0], fkey(v));
    }
}

// One block per row r: rr = yn/max - y in SMEM, then X2 = H * conv_i(rr[m+i]),
// write unnormalized output + track global max.
__global__ void __launch_bounds__(512) k_backward(const float* __restrict__ y,
                                                  const float* __restrict__ H,
                                                  float* __restrict__ out) {
    __shared__ float srr[CTOT];
    __shared__ float sRed[16];
    const int r = blockIdx.x, tid = threadIdx.x, nt = blockDim.x;

    const float maxY = fkey_inv(g_key[0]);
    const float* ynr = g_yn + r * CTOT;
    const float* yr  = y + r * CTOT;
    for (int c = tid; c < CTOT; c += nt)
        srr[c] = ynr[c] / maxY - yr[c];
    __syncthreads();

    const float* Hr   = H   + (size_t)r * XCE;
    float*       outr = out + (size_t)r * XCE;
    float lmax = -INFINITY;
    for (int e = tid; e < XCE; e += nt) {
        int m = e / LDIM;
        int i = e - m * LDIM;
        int c = m + i;
        float v = 0.5f * srr[c];
        if (i > 0)        v += 0.25f * srr[c - 1];
        if (i < LDIM - 1) v += 0.25f * srr[c + 1];
        float o = Hr[e] * v;
        outr[e] = o;
        lmax = fmaxf(lmax, o);
    }

    int lane = tid & 31, wid = tid >> 5;
    #pragma unroll
    for (int off = 16; off; off >>= 1)
        lmax = fmaxf(lmax, __shfl_xor_sync(0xffffffffu, lmax, off));
    if (lane == 0) sRed[wid] = lmax;
    __syncthreads();
    if (wid == 0 && lane < 16) {
        float v = sRed[lane];
        #pragma unroll
        for (int off = 8; off; off >>= 1)
            v = fmaxf(v, __shfl_xor_sync(0x0000ffffu, v, off));
        if (lane == 0) atomicMax(&g_key[1], fkey(v));
    }
}

// In-place final normalization.
__global__ void k_scale(float* __restrict__ out, int n4) {
    const float inv = 1.0f / fkey_inv(g_key[1]);
    float4* o4 = (float4*)out;
    for (int j = blockIdx.x * blockDim.x + threadIdx.x; j < n4; j += gridDim.x * blockDim.x) {
        float4 v = o4[j];
        v.x *= inv; v.y *= inv; v.z *= inv; v.w *= inv;
        o4[j] = v;
    }
}

extern "C" void kernel_launch(void* const* d_in, const int* in_sizes, int n_in,
                              void* d_out, int out_size) {
    // Identify inputs by element count (robust to ordering)
    const float *X = 0, *y = 0, *H = 0;
    for (int i = 0; i < n_in; ++i) {
        if      (in_sizes[i] == NX * NX * LDIM)     X = (const float*)d_in[i];
        else if (in_sizes[i] == MDIM * CTOT)        y = (const float*)d_in[i];
        else if (in_sizes[i] == MDIM * MDIM * LDIM) H = (const float*)d_in[i];
    }
    float* out = (float*)d_out;

    cudaFuncSetAttribute(k_forward, cudaFuncAttributeMaxDynamicSharedMemorySize,
                         (int)SMEM_FWD);

    k_init<<<1, 1>>>();
    k_forward<<<MDIM, 1024, SMEM_FWD>>>(X, H);
    k_backward<<<MDIM, 512>>>(y, H, out);
    k_scale<<<2048, 256>>>(out, (MDIM * MDIM * LDIM) / 4);
}